// round 1
// baseline (speedup 1.0000x reference)
#include <cuda_runtime.h>

#define BATCH 16384
#define NNZ   819200
#define KDIM  16
#define VOCAB 1000000

// Scratch (allocation-free rule: __device__ globals)
__device__ int g_row_ptr[BATCH + 1];
__device__ int g_is64;

// ---------------------------------------------------------------------------
// Detect whether index/feats buffers are int64 or int32.
// Interpreted as int64, high words of mid-array elements must be 0 (values <
// 2^31). Interpreted as int32, those words are sorted index values ~8192 != 0.
// Reads stay in-bounds under BOTH interpretations (word 2i+1, i < NNZ/2).
// ---------------------------------------------------------------------------
__global__ void detect_kernel(const unsigned int* __restrict__ idx_words) {
    if (threadIdx.x == 0 && blockIdx.x == 0) {
        unsigned int acc = 0;
        int base = NNZ / 2 - 8;
#pragma unroll
        for (int i = 0; i < 8; i++) acc |= idx_words[2 * (base + i) + 1];
        g_is64 = (acc == 0u) ? 1 : 0;
    }
}

__device__ __forceinline__ long long load_i(const void* __restrict__ p, int i, int is64) {
    if (is64) return __ldg(((const long long*)p) + i);
    return (long long)__ldg(((const int*)p) + i);
}

// ---------------------------------------------------------------------------
// row_ptr[b] = lower_bound(index, b).  index is sorted.
// ---------------------------------------------------------------------------
__global__ void rowptr_kernel(const void* __restrict__ index) {
    int b = blockIdx.x * blockDim.x + threadIdx.x;
    if (b > BATCH) return;
    int is64 = g_is64;
    int lo = 0, hi = NNZ;
    while (lo < hi) {
        int mid = (lo + hi) >> 1;
        if (load_i(index, mid, is64) < (long long)b) lo = mid + 1;
        else hi = mid;
    }
    g_row_ptr[b] = lo;
}

// ---------------------------------------------------------------------------
// Warp per row. Lanes = 2 groups x 16 k-lanes.
//   group g handles nonzeros j = s+g, s+g+2, ...
//   lane's k = lane & 15 accumulates t1_k; all lanes accumulate scalar t2;
//   lanes with k==0 accumulate the first-order term.
// Final: combine halves with shfl_xor(16), then full 32-lane butterfly of
//   r = 0.25*t1c^2 - 0.5*t2 + first
// which sums to first_tot + 0.5*(sum_k t1_k^2 - t2_tot). No atomics.
// ---------------------------------------------------------------------------
__global__ void __launch_bounds__(256)
fm_kernel(const void* __restrict__ feats,
          const float* __restrict__ values,
          const float* __restrict__ weights,
          const float* __restrict__ embedding,
          const float* __restrict__ bias,
          float* __restrict__ out) {
    int warp = (blockIdx.x * blockDim.x + threadIdx.x) >> 5;
    int lane = threadIdx.x & 31;
    if (warp >= BATCH) return;

    const int b = warp;
    const int s = g_row_ptr[b];
    const int e = g_row_ptr[b + 1];
    const int is64 = g_is64;
    const int k = lane & 15;
    const int g = lane >> 4;

    float t1 = 0.f, t2 = 0.f, first = 0.f;

    int j = s + g;
    if (j < e) {
        // software-pipeline the (feats, values) loads one step ahead
        long long f_cur = load_i(feats, j, is64);
        float     v_cur = __ldg(values + j);
        for (; j < e; j += 2) {
            long long f = f_cur;
            float     v = v_cur;
            int jn = j + 2;
            if (jn < e) {
                f_cur = load_i(feats, jn, is64);
                v_cur = __ldg(values + jn);
            }
            int fi = (int)f;
            float ev = __ldg(embedding + (size_t)fi * KDIM + k) * v;
            t1 += ev;
            t2 += ev * ev;
            if (k == 0) first += __ldg(weights + fi) * v;
        }
    }

    // combine the two 16-lane groups' t1_k
    t1 += __shfl_xor_sync(0xffffffffu, t1, 16);

    // per-lane partial; see header comment for the 0.25/0.5 factors
    float r = 0.25f * t1 * t1 - 0.5f * t2 + first;
#pragma unroll
    for (int o = 16; o > 0; o >>= 1)
        r += __shfl_xor_sync(0xffffffffu, r, o);

    if (lane == 0) {
        float x = r + __ldg(bias);
        out[b] = 1.0f / (1.0f + expf(-x));
    }
}

// ---------------------------------------------------------------------------
extern "C" void kernel_launch(void* const* d_in, const int* in_sizes, int n_in,
                              void* d_out, int out_size) {
    const void*  index_p  = nullptr;
    const void*  feats_p  = nullptr;
    const float* values_p = nullptr;
    const float* bias_p   = nullptr;
    const float* weights_p = nullptr;
    const float* embed_p  = nullptr;

    int triple = 0;
    for (int i = 0; i < n_in; i++) {
        int sz = in_sizes[i];
        if (sz == NNZ) {
            if      (triple == 0) index_p  = d_in[i];
            else if (triple == 1) feats_p  = d_in[i];
            else                  values_p = (const float*)d_in[i];
            triple++;
        } else if (sz == VOCAB) {
            weights_p = (const float*)d_in[i];
        } else if (sz == VOCAB * KDIM) {
            embed_p = (const float*)d_in[i];
        } else if (sz == 1) {
            bias_p = (const float*)d_in[i];   // batch_size (if present) comes
                                              // first; bias is the LAST size-1
        }
    }

    float* out = (float*)d_out;
    (void)out_size;

    detect_kernel<<<1, 32>>>((const unsigned int*)index_p);
    rowptr_kernel<<<(BATCH + 1 + 255) / 256, 256>>>(index_p);
    fm_kernel<<<(BATCH * 32 + 255) / 256, 256>>>(feats_p, values_p, weights_p,
                                                 embed_p, bias_p, out);
}

// round 2
// speedup vs baseline: 1.5985x; 1.5985x over previous
#include <cuda_runtime.h>

#define BATCH 16384
#define NNZ   819200
#define KDIM  16
#define VOCAB 1000000

// ---------------------------------------------------------------------------
// Single fused kernel: warp per batch row.
//  - int64/int32 dtype detection inline (high words of mid-array index elems)
//  - row range via per-warp binary search on sorted `index`
//  - chunks of 32 nonzeros: coalesced (feat, value) loads, per-lane
//    first-order gather, then 8-groups-of-4-lanes float4 embedding loads
//    (8 nonzeros per LDG.128), shfl-broadcast of (f, v).
//  - per-lane partials folded with one butterfly at the end. No atomics.
// ---------------------------------------------------------------------------

__device__ __forceinline__ float warp_sum(float r) {
#pragma unroll
    for (int o = 16; o > 0; o >>= 1)
        r += __shfl_xor_sync(0xffffffffu, r, o);
    return r;
}

__global__ void __launch_bounds__(256)
fm_fused_kernel(const void* __restrict__ index,
                const void* __restrict__ feats,
                const float* __restrict__ values,
                const float* __restrict__ weights,
                const float* __restrict__ embedding,
                const float* __restrict__ bias,
                float* __restrict__ out) {
    const int warp = (blockIdx.x * blockDim.x + threadIdx.x) >> 5;
    const int lane = threadIdx.x & 31;
    if (warp >= BATCH) return;
    const int b = warp;

    // ---- dtype detection (lane 0, broadcast). In-bounds under both views. ----
    int is64;
    if (lane == 0) {
        const unsigned int* w = (const unsigned int*)index;
        unsigned int acc = 0;
        int base = NNZ / 2 - 8;
#pragma unroll
        for (int i = 0; i < 8; i++) acc |= w[2 * (base + i) + 1];
        is64 = (acc == 0u) ? 1 : 0;
    }
    is64 = __shfl_sync(0xffffffffu, is64, 0);

    // ---- row range: lanes search lower_bound(b + min(lane,1)) ----
    const long long target = (long long)(b + (lane ? 1 : 0));
    int lo = 0, hi = NNZ;
    if (is64) {
        const long long* idx = (const long long*)index;
        while (lo < hi) {
            int mid = (lo + hi) >> 1;
            if (__ldg(idx + mid) < target) lo = mid + 1; else hi = mid;
        }
    } else {
        const int* idx = (const int*)index;
        const int t32 = (int)target;
        while (lo < hi) {
            int mid = (lo + hi) >> 1;
            if (__ldg(idx + mid) < t32) lo = mid + 1; else hi = mid;
        }
    }
    const int s = __shfl_sync(0xffffffffu, lo, 0);
    const int e = __shfl_sync(0xffffffffu, lo, 1);

    // ---- accumulation ----
    const int g = lane >> 2;   // group 0..7 (which nonzero within an octet)
    const int m = lane & 3;    // float4 slot: covers k = 4m .. 4m+3

    float4 t1 = make_float4(0.f, 0.f, 0.f, 0.f);
    float  t2 = 0.f, first = 0.f;

    for (int base = s; base < e; base += 32) {
        const int j = base + lane;
        int   f = 0;
        float v = 0.f;
        if (j < e) {
            f = is64 ? (int)__ldg((const long long*)feats + j)
                     : __ldg((const int*)feats + j);
            v = __ldg(values + j);
        }
        // first-order: one coalesced-gather instruction for 32 nnz
        first += __ldg(weights + f) * v;

        const int frow = f * KDIM;
#pragma unroll
        for (int t = 0; t < 4; t++) {
            const int   src = 8 * t + g;
            const int   fr  = __shfl_sync(0xffffffffu, frow, src);
            const float vv  = __shfl_sync(0xffffffffu, v,    src);
            const float4 ev4 = __ldg((const float4*)(embedding + fr) + m);
            const float e0 = ev4.x * vv, e1 = ev4.y * vv,
                        e2 = ev4.z * vv, e3 = ev4.w * vv;
            t1.x += e0; t1.y += e1; t1.z += e2; t1.w += e3;
            t2   += e0 * e0 + e1 * e1 + e2 * e2 + e3 * e3;
        }
    }

    // combine t1 across the 8 groups (group bits = lane bits 2..4)
#pragma unroll
    for (int o = 4; o <= 16; o <<= 1) {
        t1.x += __shfl_xor_sync(0xffffffffu, t1.x, o);
        t1.y += __shfl_xor_sync(0xffffffffu, t1.y, o);
        t1.z += __shfl_xor_sync(0xffffffffu, t1.z, o);
        t1.w += __shfl_xor_sync(0xffffffffu, t1.w, o);
    }

    // Each of the 8 lane-replicas per m-slot holds full t1_k for its 4 ks.
    // Sum over 32 lanes counts each k 8 times -> coefficient 0.5/8 = 0.0625.
    float r = 0.0625f * (t1.x * t1.x + t1.y * t1.y + t1.z * t1.z + t1.w * t1.w)
            - 0.5f * t2 + first;
    r = warp_sum(r);

    if (lane == 0) {
        const float x = r + __ldg(bias);
        out[b] = 1.0f / (1.0f + expf(-x));
    }
}

// ---------------------------------------------------------------------------
extern "C" void kernel_launch(void* const* d_in, const int* in_sizes, int n_in,
                              void* d_out, int out_size) {
    const void*  index_p   = nullptr;
    const void*  feats_p   = nullptr;
    const float* values_p  = nullptr;
    const float* bias_p    = nullptr;
    const float* weights_p = nullptr;
    const float* embed_p   = nullptr;

    int triple = 0;
    for (int i = 0; i < n_in; i++) {
        int sz = in_sizes[i];
        if (sz == NNZ) {
            if      (triple == 0) index_p  = d_in[i];
            else if (triple == 1) feats_p  = d_in[i];
            else                  values_p = (const float*)d_in[i];
            triple++;
        } else if (sz == VOCAB) {
            weights_p = (const float*)d_in[i];
        } else if (sz == VOCAB * KDIM) {
            embed_p = (const float*)d_in[i];
        } else if (sz == 1) {
            bias_p = (const float*)d_in[i];   // last size-1 input is bias
        }
    }

    float* out = (float*)d_out;
    (void)out_size;

    const int warps  = BATCH;
    const int blocks = (warps * 32 + 255) / 256;
    fm_fused_kernel<<<blocks, 256>>>(index_p, feats_p, values_p,
                                     weights_p, embed_p, bias_p, out);
}